// round 6
// baseline (speedup 1.0000x reference)
#include <cuda_runtime.h>
#include <cuda_bf16.h>
#include <cstdint>

#define Bn 16
#define Ln 4096
#define Cn 1024
#define Kn 16
#define NEG_INF (__int_as_float(0xff800000))

// ---------------- global scratch ----------------
__device__ float          g_scores[(size_t)Bn * Kn * Ln];   // 4MB
__device__ __nv_bfloat16  g_qhi[Kn * Cn];
__device__ __nv_bfloat16  g_qlo[Kn * Cn];
__device__ __nv_bfloat16  g_ehi[(size_t)Bn * Kn * Ln];      // 2MB
__device__ __nv_bfloat16  g_elo[(size_t)Bn * Kn * Ln];      // 2MB

// ---------------- helpers ----------------
__device__ __forceinline__ uint32_t smem_u32(const void* p) {
    return (uint32_t)__cvta_generic_to_shared(p);
}
// 128B-row swizzle (SW128 style): XOR chunk bits 4-6 with row bits 0-2
#define SWZ(x)  ((uint32_t)(x) ^ (((uint32_t)(x) >> 3) & 0x70))
// 256B-row swizzle: XOR chunk bits 4-7 with row bits 0-3
#define SWZ2(x) ((uint32_t)(x) ^ (((uint32_t)(x) >> 4) & 0xF0))

__device__ __forceinline__ void ldsm4(uint32_t a, uint32_t* r) {
    asm volatile("ldmatrix.sync.aligned.m8n8.x4.shared.b16 {%0,%1,%2,%3}, [%4];"
                 : "=r"(r[0]), "=r"(r[1]), "=r"(r[2]), "=r"(r[3]) : "r"(a));
}
__device__ __forceinline__ void ldsm4t(uint32_t a, uint32_t* r) {
    asm volatile("ldmatrix.sync.aligned.m8n8.x4.trans.shared.b16 {%0,%1,%2,%3}, [%4];"
                 : "=r"(r[0]), "=r"(r[1]), "=r"(r[2]), "=r"(r[3]) : "r"(a));
}
__device__ __forceinline__ void mma_bf16(float* d, const uint32_t* a,
                                         uint32_t b0, uint32_t b1) {
    asm volatile(
        "mma.sync.aligned.m16n8k16.row.col.f32.bf16.bf16.f32 "
        "{%0,%1,%2,%3}, {%4,%5,%6,%7}, {%8,%9}, {%0,%1,%2,%3};"
        : "+f"(d[0]), "+f"(d[1]), "+f"(d[2]), "+f"(d[3])
        : "r"(a[0]), "r"(a[1]), "r"(a[2]), "r"(a[3]), "r"(b0), "r"(b1));
}
__device__ __forceinline__ void cp16(uint32_t dst, const void* src) {
    asm volatile("cp.async.cg.shared.global [%0], [%1], 16;" :: "r"(dst), "l"(src));
}
__device__ __forceinline__ void cp_commit() {
    asm volatile("cp.async.commit_group;");
}
template <int N>
__device__ __forceinline__ void cp_wait() {
    asm volatile("cp.async.wait_group %0;" :: "n"(N) : "memory");
}
// pack (a,b) -> bf16x2 word (lo half = a, hi half = b)
__device__ __forceinline__ uint32_t bfx2(float a, float b) {
    uint32_t r;
    asm("cvt.rn.bf16x2.f32 %0, %1, %2;" : "=r"(r) : "f"(b), "f"(a));
    return r;
}
__device__ __forceinline__ void sts128(uint32_t a, uint32_t r0, uint32_t r1,
                                       uint32_t r2, uint32_t r3) {
    asm volatile("st.shared.v4.b32 [%0], {%1, %2, %3, %4};"
                 :: "r"(a), "r"(r0), "r"(r1), "r"(r2), "r"(r3) : "memory");
}
__device__ __forceinline__ void split8(const float* f, uint32_t* hi, uint32_t* lo) {
#pragma unroll
    for (int p = 0; p < 4; ++p) {
        uint32_t h = bfx2(f[2 * p], f[2 * p + 1]);
        float h0 = __uint_as_float(h << 16);
        float h1 = __uint_as_float(h & 0xffff0000u);
        hi[p] = h;
        lo[p] = bfx2(f[2 * p] - h0, f[2 * p + 1] - h1);
    }
}
__device__ __forceinline__ void load32(float* xr, const float* p) {
    const float4* q4 = (const float4*)p;
#pragma unroll
    for (int j = 0; j < 8; ++j) {
        float4 v = q4[j];
        xr[4 * j] = v.x; xr[4 * j + 1] = v.y;
        xr[4 * j + 2] = v.z; xr[4 * j + 3] = v.w;
    }
}

// =================== prep: split q ===================
extern "C" __global__ void __launch_bounds__(512)
prep_q(const float* __restrict__ q) {
    int i = blockIdx.x * 512 + threadIdx.x;   // 16384 total
    float f = q[i];
    __nv_bfloat16 h = __float2bfloat16(f);
    g_qhi[i] = h;
    g_qlo[i] = __float2bfloat16(f - __bfloat162float(h));
}

// =================== Pass 1: scores = x @ q^T ===================
// smem: QH 16 tiles*2KB, QL same, X double buffer (hi32K+lo32K)*2, mask
#define P1_QH   0
#define P1_QL   32768
#define P1_XB0  65536
#define P1_XB1  131072
#define P1_MK   196608
#define P1_SMEM 197632

extern "C" __global__ void __launch_bounds__(512, 1)
pass1_scores(const float* __restrict__ x, const int* __restrict__ mask) {
    extern __shared__ char smem[];
    const uint32_t sb = smem_u32(smem);
    const int tid = threadIdx.x, w = tid >> 5, lane = tid & 31;
    const int b = blockIdx.x >> 4, split = blockIdx.x & 15;
    const int l0 = split * 256;
    const float* xb = x + ((size_t)b * Ln + l0) * Cn;
    int* mask_s = (int*)(smem + P1_MK);
    if (tid < 256) mask_s[tid] = mask[b * Ln + l0 + tid];

    // stage q hi/lo (all 16 c-tiles of 64) via cp.async
#pragma unroll
    for (int i = 0; i < 4; ++i) {
        int id = tid + 512 * i;               // 0..2047
        int t = id >> 7, r = (id >> 3) & 15, j = id & 7;
        uint32_t o = t * 2048 + SWZ(r * 128 + j * 16);
        cp16(sb + P1_QH + o, g_qhi + r * Cn + t * 64 + j * 8);
        cp16(sb + P1_QL + o, g_qlo + r * Cn + t * 64 + j * 8);
    }
    cp_commit();

    const int row = tid >> 1, ch = (tid & 1) * 32;   // 256 rows x 64c tile
    float xr[32];
    load32(xr, xb + (size_t)row * Cn + ch);

    float acc0[4] = {0.f, 0.f, 0.f, 0.f};
    float acc1[4] = {0.f, 0.f, 0.f, 0.f};

    // lane constants for fragments
    const int lrowA = w * 16 + (lane & 15);
    const int caA = (lane >> 4) * 8;
    const int rB = lane & 7, gB = lane >> 3;
    const int nB = rB + (gB >> 1) * 8;
    const int cB = (gB & 1) * 8;

    cp_wait<0>();
    __syncthreads();

    for (int t = 0; t < 16; ++t) {
        const uint32_t xh = sb + ((t & 1) ? P1_XB1 : P1_XB0);
        const uint32_t xl = xh + 32768;
        {
            uint32_t hi[4], lo[4];
#pragma unroll
            for (int g2 = 0; g2 < 4; ++g2) {
                split8(xr + 8 * g2, hi, lo);
                uint32_t o = SWZ(row * 128 + (ch + 8 * g2) * 2);
                sts128(xh + o, hi[0], hi[1], hi[2], hi[3]);
                sts128(xl + o, lo[0], lo[1], lo[2], lo[3]);
            }
        }
        if (t < 15)
            load32(xr, xb + (size_t)row * Cn + (t + 1) * 64 + ch);
        __syncthreads();

        const uint32_t qh = sb + P1_QH + t * 2048;
        const uint32_t ql = sb + P1_QL + t * 2048;
#pragma unroll
        for (int s = 0; s < 4; ++s) {
            uint32_t oA = SWZ(lrowA * 128 + (s * 16 + caA) * 2);
            uint32_t oB = SWZ(nB * 128 + (s * 16 + cB) * 2);
            uint32_t Ah[4], Al[4], Bh[4], Bl[4];
            ldsm4(xh + oA, Ah);
            ldsm4(qh + oB, Bh);
            ldsm4(xl + oA, Al);
            ldsm4(ql + oB, Bl);
            mma_bf16(acc0, Ah, Bh[0], Bh[1]);
            mma_bf16(acc1, Ah, Bh[2], Bh[3]);
            mma_bf16(acc0, Ah, Bl[0], Bl[1]);
            mma_bf16(acc1, Ah, Bl[2], Bl[3]);
            mma_bf16(acc0, Al, Bh[0], Bh[1]);
            mma_bf16(acc1, Al, Bh[2], Bh[3]);
        }
    }
    __syncthreads();

    // transpose via smem (reuse q region), then coalesced global write
    float* s_s = (float*)smem;   // [16 k][256 l]
    {
        const int m = lane >> 2, kp = (lane & 3) * 2;
        const int lb = w * 16;
        s_s[(kp    ) * 256 + lb + m    ] = acc0[0];
        s_s[(kp + 1) * 256 + lb + m    ] = acc0[1];
        s_s[(kp    ) * 256 + lb + m + 8] = acc0[2];
        s_s[(kp + 1) * 256 + lb + m + 8] = acc0[3];
        s_s[(kp + 8) * 256 + lb + m    ] = acc1[0];
        s_s[(kp + 9) * 256 + lb + m    ] = acc1[1];
        s_s[(kp + 8) * 256 + lb + m + 8] = acc1[2];
        s_s[(kp + 9) * 256 + lb + m + 8] = acc1[3];
    }
    __syncthreads();
    {
        const int k = tid >> 5, l = (tid & 31) * 8;
        float* dst = g_scores + ((size_t)(b * Kn + k)) * Ln + l0 + l;
#pragma unroll
        for (int j = 0; j < 8; ++j) {
            float v = s_s[k * 256 + l + j] * 0.03125f;
            dst[j] = mask_s[l + j] ? v : NEG_INF;
        }
    }
}

// =================== Pass 2: softmax + split weights ===================
extern "C" __global__ void __launch_bounds__(256)
pass2_softmax() {
    const int bk = blockIdx.x;
    const int tid = threadIdx.x;
    const int wid = tid >> 5;
    const int lane = tid & 31;
    __shared__ float red[8];
    __shared__ float s_m, s_d;

    const float* sc = g_scores + (size_t)bk * Ln;
    float v[16];
    float m = NEG_INF;
#pragma unroll
    for (int i = 0; i < 16; ++i) {
        v[i] = sc[i * 256 + tid];
        m = fmaxf(m, v[i]);
    }
#pragma unroll
    for (int off = 16; off; off >>= 1)
        m = fmaxf(m, __shfl_xor_sync(0xffffffffu, m, off));
    if (lane == 0) red[wid] = m;
    __syncthreads();
    if (tid == 0) {
        float mm = red[0];
#pragma unroll
        for (int i = 1; i < 8; ++i) mm = fmaxf(mm, red[i]);
        s_m = mm;
    }
    __syncthreads();
    m = s_m;

    float e[16];
    float d = 0.f;
    if (m == NEG_INF) {
#pragma unroll
        for (int i = 0; i < 16; ++i) e[i] = 0.f;
    } else {
#pragma unroll
        for (int i = 0; i < 16; ++i) { e[i] = __expf(v[i] - m); d += e[i]; }
    }
#pragma unroll
    for (int off = 16; off; off >>= 1)
        d += __shfl_xor_sync(0xffffffffu, d, off);
    if (lane == 0) red[wid] = d;
    __syncthreads();
    if (tid == 0) {
        float dd = 0.f;
#pragma unroll
        for (int i = 0; i < 8; ++i) dd += red[i];
        s_d = dd;
    }
    __syncthreads();
    d = s_d;

    const float inv = (m == NEG_INF || d <= 0.f) ? 0.f : (1.0f / d);
    __nv_bfloat16* eh = g_ehi + (size_t)bk * Ln;
    __nv_bfloat16* el = g_elo + (size_t)bk * Ln;
#pragma unroll
    for (int i = 0; i < 16; ++i) {
        float wv = e[i] * inv;
        __nv_bfloat16 h = __float2bfloat16(wv);
        eh[i * 256 + tid] = h;
        el[i * 256 + tid] = __float2bfloat16(wv - __bfloat162float(h));
    }
}

// =================== Pass 3: out = E @ x ===================
// smem: X double buffer (hi16K+lo16K)*2 = 64KB, E ring 4 slots * 4KB
#define P3_XB0  0
#define P3_XB1  32768
#define P3_E(s) (65536 + (s) * 4096)
#define P3_SMEM 81920

extern "C" __global__ void __launch_bounds__(256, 1)
pass3_pooled(const float* __restrict__ x, float* __restrict__ out) {
    extern __shared__ char smem[];
    const uint32_t sb = smem_u32(smem);
    const int tid = threadIdx.x, w = tid >> 5, lane = tid & 31;
    const int b = blockIdx.x >> 3, ct = blockIdx.x & 7;
    const float* xb = x + (size_t)b * Ln * Cn + ct * 128;

    // E tiles 0,1 prefetch (each tile: [16 k][64 l] bf16 hi+lo)
    const int eis_lo = tid >> 7, er = (tid >> 3) & 15, ej = tid & 7;
    const __nv_bfloat16* ebase =
        (eis_lo ? g_elo : g_ehi) + (size_t)(b * Kn + er) * Ln + ej * 8;
    const uint32_t eoff = eis_lo * 2048 + SWZ(er * 128 + ej * 16);
    cp16(sb + P3_E(0) + eoff, ebase);
    cp_commit();
    cp16(sb + P3_E(1) + eoff, ebase + 64);
    cp_commit();

    const int rowL = tid >> 2, cq = (tid & 3) * 32;   // 64 l x 128 c tile
    float xr[32];
    load32(xr, xb + (size_t)rowL * Cn + cq);

    float acc0[4] = {0.f, 0.f, 0.f, 0.f};
    float acc1[4] = {0.f, 0.f, 0.f, 0.f};

    const int kA = lane & 15, lhA = (lane >> 4) * 8;
    const int rB = lane & 7, gB = lane >> 3;
    const int lB = (gB & 1) * 8 + rB;
    const int cBc = w * 16 + (gB >> 1) * 8;

    for (int t = 0; t < 64; ++t) {
        const uint32_t xh = sb + ((t & 1) ? P3_XB1 : P3_XB0);
        const uint32_t xl = xh + 16384;
        {
            uint32_t hi[4], lo[4];
#pragma unroll
            for (int g2 = 0; g2 < 4; ++g2) {
                split8(xr + 8 * g2, hi, lo);
                uint32_t o = SWZ2(rowL * 256 + (cq + 8 * g2) * 2);
                sts128(xh + o, hi[0], hi[1], hi[2], hi[3]);
                sts128(xl + o, lo[0], lo[1], lo[2], lo[3]);
            }
        }
        if (t < 62)
            cp16(sb + P3_E((t + 2) & 3) + eoff, ebase + (t + 2) * 64);
        cp_commit();
        if (t < 63)
            load32(xr, xb + (size_t)((t + 1) * 64 + rowL) * Cn + cq);
        cp_wait<2>();
        __syncthreads();

        const uint32_t eh = sb + P3_E(t & 3);
        const uint32_t el = eh + 2048;
#pragma unroll
        for (int s = 0; s < 4; ++s) {
            uint32_t oA = SWZ(kA * 128 + (s * 16 + lhA) * 2);
            uint32_t oB = SWZ2((s * 16 + lB) * 256 + cBc * 2);
            uint32_t Ah[4], Al[4], Bh[4], Bl[4];
            ldsm4(eh + oA, Ah);
            ldsm4t(xh + oB, Bh);
            ldsm4(el + oA, Al);
            ldsm4t(xl + oB, Bl);
            mma_bf16(acc0, Ah, Bh[0], Bh[1]);
            mma_bf16(acc1, Ah, Bh[2], Bh[3]);
            mma_bf16(acc0, Ah, Bl[0], Bl[1]);
            mma_bf16(acc1, Ah, Bl[2], Bl[3]);
            mma_bf16(acc0, Al, Bh[0], Bh[1]);
            mma_bf16(acc1, Al, Bh[2], Bh[3]);
        }
    }

    // epilogue: direct f32x2 stores
    const int k0 = lane >> 2;
    const int c0 = w * 16 + (lane & 3) * 2;
    float* ob = out + (size_t)b * Kn * Cn + ct * 128;
    *(float2*)(ob + (size_t)k0 * Cn + c0)           = make_float2(acc0[0], acc0[1]);
    *(float2*)(ob + (size_t)(k0 + 8) * Cn + c0)     = make_float2(acc0[2], acc0[3]);
    *(float2*)(ob + (size_t)k0 * Cn + c0 + 8)       = make_float2(acc1[0], acc1[1]);
    *(float2*)(ob + (size_t)(k0 + 8) * Cn + c0 + 8) = make_float2(acc1[2], acc1[3]);
}

extern "C" void kernel_launch(void* const* d_in, const int* in_sizes, int n_in,
                              void* d_out, int out_size) {
    const float* x  = (const float*)d_in[0];
    const int* mask = (const int*)d_in[1];
    const float* q  = (const float*)d_in[2];
    float* out      = (float*)d_out;

    cudaFuncSetAttribute(pass1_scores,
                         cudaFuncAttributeMaxDynamicSharedMemorySize, P1_SMEM);
    cudaFuncSetAttribute(pass3_pooled,
                         cudaFuncAttributeMaxDynamicSharedMemorySize, P3_SMEM);

    prep_q<<<32, 512>>>(q);
    pass1_scores<<<Bn * 16, 512, P1_SMEM>>>(x, mask);
    pass2_softmax<<<Bn * Kn, 256>>>();
    pass3_pooled<<<Bn * 8, 256, P3_SMEM>>>(x, out);
}

// round 7
// speedup vs baseline: 1.0284x; 1.0284x over previous
#include <cuda_runtime.h>
#include <cuda_bf16.h>
#include <cstdint>

#define Bn 16
#define Ln 4096
#define Cn 1024
#define Kn 16
#define NEG_INF (__int_as_float(0xff800000))

// ---------------- global scratch ----------------
__device__ float          g_scores[(size_t)Bn * Kn * Ln];   // 4MB
__device__ __nv_bfloat16  g_qhi[Kn * Cn];
__device__ __nv_bfloat16  g_qlo[Kn * Cn];
__device__ __nv_bfloat16  g_ehi[(size_t)Bn * Kn * Ln];      // 2MB
__device__ __nv_bfloat16  g_elo[(size_t)Bn * Kn * Ln];      // 2MB
__device__ float          g_p0[(size_t)Bn * Kn * Cn];       // 1MB partial (l-half 0)
__device__ float          g_p1[(size_t)Bn * Kn * Cn];       // 1MB partial (l-half 1)

// ---------------- helpers ----------------
__device__ __forceinline__ uint32_t smem_u32(const void* p) {
    return (uint32_t)__cvta_generic_to_shared(p);
}
#define SWZ(x)  ((uint32_t)(x) ^ (((uint32_t)(x) >> 3) & 0x70))
#define SWZ2(x) ((uint32_t)(x) ^ (((uint32_t)(x) >> 4) & 0xF0))

__device__ __forceinline__ void ldsm4(uint32_t a, uint32_t* r) {
    asm volatile("ldmatrix.sync.aligned.m8n8.x4.shared.b16 {%0,%1,%2,%3}, [%4];"
                 : "=r"(r[0]), "=r"(r[1]), "=r"(r[2]), "=r"(r[3]) : "r"(a));
}
__device__ __forceinline__ void ldsm4t(uint32_t a, uint32_t* r) {
    asm volatile("ldmatrix.sync.aligned.m8n8.x4.trans.shared.b16 {%0,%1,%2,%3}, [%4];"
                 : "=r"(r[0]), "=r"(r[1]), "=r"(r[2]), "=r"(r[3]) : "r"(a));
}
__device__ __forceinline__ void mma_bf16(float* d, const uint32_t* a,
                                         uint32_t b0, uint32_t b1) {
    asm volatile(
        "mma.sync.aligned.m16n8k16.row.col.f32.bf16.bf16.f32 "
        "{%0,%1,%2,%3}, {%4,%5,%6,%7}, {%8,%9}, {%0,%1,%2,%3};"
        : "+f"(d[0]), "+f"(d[1]), "+f"(d[2]), "+f"(d[3])
        : "r"(a[0]), "r"(a[1]), "r"(a[2]), "r"(a[3]), "r"(b0), "r"(b1));
}
__device__ __forceinline__ void cp16(uint32_t dst, const void* src) {
    asm volatile("cp.async.cg.shared.global [%0], [%1], 16;" :: "r"(dst), "l"(src));
}
__device__ __forceinline__ void cp_commit() {
    asm volatile("cp.async.commit_group;");
}
template <int N>
__device__ __forceinline__ void cp_wait() {
    asm volatile("cp.async.wait_group %0;" :: "n"(N) : "memory");
}
__device__ __forceinline__ uint32_t bfx2(float a, float b) {
    uint32_t r;
    asm("cvt.rn.bf16x2.f32 %0, %1, %2;" : "=r"(r) : "f"(b), "f"(a));
    return r;
}
__device__ __forceinline__ void sts128(uint32_t a, uint32_t r0, uint32_t r1,
                                       uint32_t r2, uint32_t r3) {
    asm volatile("st.shared.v4.b32 [%0], {%1, %2, %3, %4};"
                 :: "r"(a), "r"(r0), "r"(r1), "r"(r2), "r"(r3) : "memory");
}
__device__ __forceinline__ void split8(const float* f, uint32_t* hi, uint32_t* lo) {
#pragma unroll
    for (int p = 0; p < 4; ++p) {
        uint32_t h = bfx2(f[2 * p], f[2 * p + 1]);
        float h0 = __uint_as_float(h << 16);
        float h1 = __uint_as_float(h & 0xffff0000u);
        hi[p] = h;
        lo[p] = bfx2(f[2 * p] - h0, f[2 * p + 1] - h1);
    }
}
__device__ __forceinline__ void load32(float* xr, const float* p) {
    const float4* q4 = (const float4*)p;
#pragma unroll
    for (int j = 0; j < 8; ++j) {
        float4 v = q4[j];
        xr[4 * j] = v.x; xr[4 * j + 1] = v.y;
        xr[4 * j + 2] = v.z; xr[4 * j + 3] = v.w;
    }
}

// =================== prep: split q ===================
extern "C" __global__ void __launch_bounds__(512)
prep_q(const float* __restrict__ q) {
    int i = blockIdx.x * 512 + threadIdx.x;
    float f = q[i];
    __nv_bfloat16 h = __float2bfloat16(f);
    g_qhi[i] = h;
    g_qlo[i] = __float2bfloat16(f - __bfloat162float(h));
}

// =================== Pass 1: scores = x @ q^T ===================
// block: 128 l x 16 k, K-loop 16 c-tiles of 64.  grid 512, 2 blocks/SM.
#define P1_X0   0                       // hi 16KB + lo 16KB
#define P1_X1   32768
#define P1_QR(s) (65536 + (s) * 4096)   // ring: hi 2KB + lo 2KB per slot
#define P1_MK   81920
#define P1_SMEM 82432

extern "C" __global__ void __launch_bounds__(256, 2)
pass1_scores(const float* __restrict__ x, const int* __restrict__ mask) {
    extern __shared__ char smem[];
    const uint32_t sb = smem_u32(smem);
    const int tid = threadIdx.x, w = tid >> 5, lane = tid & 31;
    const int b = blockIdx.x >> 5, split = blockIdx.x & 31;
    const int l0 = split * 128;
    const float* xb = x + ((size_t)b * Ln + l0) * Cn;
    int* mask_s = (int*)(smem + P1_MK);
    if (tid < 128) mask_s[tid] = mask[b * Ln + l0 + tid];

    // q ring: one cp16 per thread per slot
    const int qis_lo = tid >> 7;                       // 0/1
    const int qr = (tid >> 3) & 15, qj = tid & 7;
    const __nv_bfloat16* qbase = (qis_lo ? g_qlo : g_qhi) + qr * Cn + qj * 8;
    const uint32_t qoff = qis_lo * 2048 + SWZ(qr * 128 + qj * 16);
    cp16(sb + P1_QR(0) + qoff, qbase);
    cp_commit();
    cp16(sb + P1_QR(1) + qoff, qbase + 64);
    cp_commit();

    // depth-2 register prefetch of x
    const int row = tid >> 1, ch = (tid & 1) * 32;     // 128 rows x 64 c
    float xrA[32], xrB[32];
    load32(xrA, xb + (size_t)row * Cn + ch);           // tile 0
    load32(xrB, xb + (size_t)row * Cn + 64 + ch);      // tile 1

    float acc0[4] = {0.f, 0.f, 0.f, 0.f};
    float acc1[4] = {0.f, 0.f, 0.f, 0.f};

    const int lrowA = w * 16 + (lane & 15);
    const int caA = (lane >> 4) * 8;
    const int rB = lane & 7, gB = lane >> 3;
    const int nB = rB + (gB >> 1) * 8;
    const int cB = (gB & 1) * 8;

    for (int t = 0; t < 16; ++t) {
        float* xr = (t & 1) ? xrB : xrA;
        const uint32_t xh = sb + ((t & 1) ? P1_X1 : P1_X0);
        const uint32_t xl = xh + 16384;
        {
            uint32_t hi[4], lo[4];
#pragma unroll
            for (int g2 = 0; g2 < 4; ++g2) {
                split8(xr + 8 * g2, hi, lo);
                uint32_t o = SWZ(row * 128 + (ch + 8 * g2) * 2);
                sts128(xh + o, hi[0], hi[1], hi[2], hi[3]);
                sts128(xl + o, lo[0], lo[1], lo[2], lo[3]);
            }
        }
        if (t < 14) {
            load32(xr, xb + (size_t)row * Cn + (t + 2) * 64 + ch);  // tile t+2
            cp16(sb + P1_QR((t + 2) & 3) + qoff, qbase + (t + 2) * 64);
        }
        cp_commit();
        cp_wait<2>();
        __syncthreads();

        const uint32_t qh = sb + P1_QR(t & 3);
        const uint32_t ql = qh + 2048;
#pragma unroll
        for (int s = 0; s < 4; ++s) {
            uint32_t oA = SWZ(lrowA * 128 + (s * 16 + caA) * 2);
            uint32_t oB = SWZ(nB * 128 + (s * 16 + cB) * 2);
            uint32_t Ah[4], Al[4], Bh[4], Bl[4];
            ldsm4(xh + oA, Ah);
            ldsm4(qh + oB, Bh);
            ldsm4(xl + oA, Al);
            ldsm4(ql + oB, Bl);
            mma_bf16(acc0, Ah, Bh[0], Bh[1]);
            mma_bf16(acc1, Ah, Bh[2], Bh[3]);
            mma_bf16(acc0, Ah, Bl[0], Bl[1]);
            mma_bf16(acc1, Ah, Bl[2], Bl[3]);
            mma_bf16(acc0, Al, Bh[0], Bh[1]);
            mma_bf16(acc1, Al, Bh[2], Bh[3]);
        }
    }
    __syncthreads();

    // transpose via smem, then coalesced masked write
    float* s_s = (float*)smem;   // [16 k][128 l] (reuses X0)
    {
        const int m = lane >> 2, kp = (lane & 3) * 2;
        const int lb = w * 16;
        s_s[(kp    ) * 128 + lb + m    ] = acc0[0];
        s_s[(kp + 1) * 128 + lb + m    ] = acc0[1];
        s_s[(kp    ) * 128 + lb + m + 8] = acc0[2];
        s_s[(kp + 1) * 128 + lb + m + 8] = acc0[3];
        s_s[(kp + 8) * 128 + lb + m    ] = acc1[0];
        s_s[(kp + 9) * 128 + lb + m    ] = acc1[1];
        s_s[(kp + 8) * 128 + lb + m + 8] = acc1[2];
        s_s[(kp + 9) * 128 + lb + m + 8] = acc1[3];
    }
    __syncthreads();
    {
        const int k = tid >> 4, l = (tid & 15) * 8;
        float* dst = g_scores + ((size_t)(b * Kn + k)) * Ln + l0 + l;
#pragma unroll
        for (int j = 0; j < 8; ++j) {
            float v = s_s[k * 128 + l + j] * 0.03125f;
            dst[j] = mask_s[l + j] ? v : NEG_INF;
        }
    }
}

// =================== Pass 2: softmax + split weights ===================
extern "C" __global__ void __launch_bounds__(256)
pass2_softmax() {
    const int bk = blockIdx.x;
    const int tid = threadIdx.x;
    const int wid = tid >> 5;
    const int lane = tid & 31;
    __shared__ float red[8];
    __shared__ float s_m, s_d;

    const float* sc = g_scores + (size_t)bk * Ln;
    float v[16];
    float m = NEG_INF;
#pragma unroll
    for (int i = 0; i < 16; ++i) {
        v[i] = sc[i * 256 + tid];
        m = fmaxf(m, v[i]);
    }
#pragma unroll
    for (int off = 16; off; off >>= 1)
        m = fmaxf(m, __shfl_xor_sync(0xffffffffu, m, off));
    if (lane == 0) red[wid] = m;
    __syncthreads();
    if (tid == 0) {
        float mm = red[0];
#pragma unroll
        for (int i = 1; i < 8; ++i) mm = fmaxf(mm, red[i]);
        s_m = mm;
    }
    __syncthreads();
    m = s_m;

    float e[16];
    float d = 0.f;
    if (m == NEG_INF) {
#pragma unroll
        for (int i = 0; i < 16; ++i) e[i] = 0.f;
    } else {
#pragma unroll
        for (int i = 0; i < 16; ++i) { e[i] = __expf(v[i] - m); d += e[i]; }
    }
#pragma unroll
    for (int off = 16; off; off >>= 1)
        d += __shfl_xor_sync(0xffffffffu, d, off);
    if (lane == 0) red[wid] = d;
    __syncthreads();
    if (tid == 0) {
        float dd = 0.f;
#pragma unroll
        for (int i = 0; i < 8; ++i) dd += red[i];
        s_d = dd;
    }
    __syncthreads();
    d = s_d;

    const float inv = (m == NEG_INF || d <= 0.f) ? 0.f : (1.0f / d);
    __nv_bfloat16* eh = g_ehi + (size_t)bk * Ln;
    __nv_bfloat16* el = g_elo + (size_t)bk * Ln;
#pragma unroll
    for (int i = 0; i < 16; ++i) {
        float wv = e[i] * inv;
        __nv_bfloat16 h = __float2bfloat16(wv);
        eh[i * 256 + tid] = h;
        el[i * 256 + tid] = __float2bfloat16(wv - __bfloat162float(h));
    }
}

// =================== Pass 3: partial = E @ x (l-halves) ===================
#define P3_X0   0                       // hi 16KB + lo 16KB
#define P3_X1   32768
#define P3_E(s) (65536 + (s) * 4096)    // ring: hi 2KB + lo 2KB per slot
#define P3_SMEM 81920

extern "C" __global__ void __launch_bounds__(256, 2)
pass3_pooled(const float* __restrict__ x) {
    extern __shared__ char smem[];
    const uint32_t sb = smem_u32(smem);
    const int tid = threadIdx.x, w = tid >> 5, lane = tid & 31;
    const int b = blockIdx.x >> 4;
    const int ct = blockIdx.x & 7;
    const int lh = (blockIdx.x >> 3) & 1;
    const float* xb = x + (size_t)b * Ln * Cn + (size_t)lh * 2048 * Cn + ct * 128;

    // E ring: one cp16 per thread per slot
    const int eis_lo = tid >> 7, er = (tid >> 3) & 15, ej = tid & 7;
    const __nv_bfloat16* ebase =
        (eis_lo ? g_elo : g_ehi) + (size_t)(b * Kn + er) * Ln + lh * 2048 + ej * 8;
    const uint32_t eoff = eis_lo * 2048 + SWZ(er * 128 + ej * 16);
    cp16(sb + P3_E(0) + eoff, ebase);
    cp_commit();
    cp16(sb + P3_E(1) + eoff, ebase + 64);
    cp_commit();

    // depth-2 register prefetch of x
    const int rowL = tid >> 2, cq = (tid & 3) * 32;    // 64 l x 128 c
    float xrA[32], xrB[32];
    load32(xrA, xb + (size_t)rowL * Cn + cq);
    load32(xrB, xb + (size_t)(64 + rowL) * Cn + cq);

    float acc0[4] = {0.f, 0.f, 0.f, 0.f};
    float acc1[4] = {0.f, 0.f, 0.f, 0.f};

    const int kA = lane & 15, lhA = (lane >> 4) * 8;
    const int rB = lane & 7, gB = lane >> 3;
    const int lB = (gB & 1) * 8 + rB;
    const int cBc = w * 16 + (gB >> 1) * 8;

    for (int t = 0; t < 32; ++t) {
        float* xr = (t & 1) ? xrB : xrA;
        const uint32_t xh = sb + ((t & 1) ? P3_X1 : P3_X0);
        const uint32_t xl = xh + 16384;
        {
            uint32_t hi[4], lo[4];
#pragma unroll
            for (int g2 = 0; g2 < 4; ++g2) {
                split8(xr + 8 * g2, hi, lo);
                uint32_t o = SWZ2(rowL * 256 + (cq + 8 * g2) * 2);
                sts128(xh + o, hi[0], hi[1], hi[2], hi[3]);
                sts128(xl + o, lo[0], lo[1], lo[2], lo[3]);
            }
        }
        if (t < 30) {
            load32(xr, xb + (size_t)((t + 2) * 64 + rowL) * Cn + cq);
            cp16(sb + P3_E((t + 2) & 3) + eoff, ebase + (t + 2) * 64);
        }
        cp_commit();
        cp_wait<2>();
        __syncthreads();

        const uint32_t eh = sb + P3_E(t & 3);
        const uint32_t el = eh + 2048;
#pragma unroll
        for (int s = 0; s < 4; ++s) {
            uint32_t oA = SWZ(kA * 128 + (s * 16 + lhA) * 2);
            uint32_t oB = SWZ2((s * 16 + lB) * 256 + cBc * 2);
            uint32_t Ah[4], Al[4], Bh[4], Bl[4];
            ldsm4(eh + oA, Ah);
            ldsm4t(xh + oB, Bh);
            ldsm4(el + oA, Al);
            ldsm4t(xl + oB, Bl);
            mma_bf16(acc0, Ah, Bh[0], Bh[1]);
            mma_bf16(acc1, Ah, Bh[2], Bh[3]);
            mma_bf16(acc0, Ah, Bl[0], Bl[1]);
            mma_bf16(acc1, Ah, Bl[2], Bl[3]);
            mma_bf16(acc0, Al, Bh[0], Bh[1]);
            mma_bf16(acc1, Al, Bh[2], Bh[3]);
        }
    }

    // epilogue: partial fp32 stores
    float* pb = (lh ? g_p1 : g_p0) + (size_t)b * Kn * Cn + ct * 128;
    const int k0 = lane >> 2;
    const int c0 = w * 16 + (lane & 3) * 2;
    *(float2*)(pb + (size_t)k0 * Cn + c0)           = make_float2(acc0[0], acc0[1]);
    *(float2*)(pb + (size_t)(k0 + 8) * Cn + c0)     = make_float2(acc0[2], acc0[3]);
    *(float2*)(pb + (size_t)k0 * Cn + c0 + 8)       = make_float2(acc1[0], acc1[1]);
    *(float2*)(pb + (size_t)(k0 + 8) * Cn + c0 + 8) = make_float2(acc1[2], acc1[3]);
}

// =================== merge: out = p0 + p1 ===================
extern "C" __global__ void __launch_bounds__(512)
merge_out(float* __restrict__ out) {
    const int i = blockIdx.x * 512 + threadIdx.x;    // 65536 float4
    float4 a = ((const float4*)g_p0)[i];
    float4 c = ((const float4*)g_p1)[i];
    ((float4*)out)[i] = make_float4(a.x + c.x, a.y + c.y, a.z + c.z, a.w + c.w);
}

extern "C" void kernel_launch(void* const* d_in, const int* in_sizes, int n_in,
                              void* d_out, int out_size) {
    const float* x  = (const float*)d_in[0];
    const int* mask = (const int*)d_in[1];
    const float* q  = (const float*)d_in[2];
    float* out      = (float*)d_out;

    cudaFuncSetAttribute(pass1_scores,
                         cudaFuncAttributeMaxDynamicSharedMemorySize, P1_SMEM);
    cudaFuncSetAttribute(pass3_pooled,
                         cudaFuncAttributeMaxDynamicSharedMemorySize, P3_SMEM);

    prep_q<<<32, 512>>>(q);
    pass1_scores<<<Bn * 32, 256, P1_SMEM>>>(x, mask);
    pass2_softmax<<<Bn * Kn, 256>>>();
    pass3_pooled<<<Bn * 16, 256, P3_SMEM>>>(x);
    merge_out<<<128, 512>>>(out);
}